// round 7
// baseline (speedup 1.0000x reference)
#include <cuda_runtime.h>

#define NB     2048
#define NOH    20
#define NOTH   23
#define NC     10
#define SC     200      // NOH*NC
#define EMB    9
#define OUTC   32
#define XSTR   43       // NOH + NOTH
#define HW     2304     // 48*48
#define SLABSZ 73728    // OUTC*HW floats per batch

#define THREADS 576

// Dynamic smem layout (float offsets), all float4-aligned
#define OFF_V     0          // 18432  v[b*9+e]
#define OFF_FCW   18432      // 1800
#define OFF_W     20232      // 1024   fused 32x32 weight
#define OFF_CB    21256      // 32     fused bias
#define OFF_FCB   21288      // 12     fc_b
#define OFF_XC    21300      // 5504   x-chunk buffer (128 rows x 43)
#define OFF_TILE  26804      // 9216   [ch][m]
#define SMEM_FLOATS 36020    // 144080 bytes

// Single fused kernel. Grid (c:8, og:8, bs:2) = 128 CTAs x 576 threads, 1/SM.
// CTA: (1) fold weights, (2) compute ALL 2048 embedding rows via chunked
// coalesced x staging (fixes R5's replay storm), (3) compute its 4-channel x
// all-m tile (36 KB contiguous in output), (4) store it for 128 batches with
// a per-CTA staggered batch order (fixes R4/R6's lockstep channel hotspot).
//
// Verified identities (rel_err ~1.4e-7, R1-R6):
//   out[b][o][m] depends on b only through c = b & 7
//   three 1x1 convs fold into one 32x32 weight W + bias cb
//   slab[c][o][m] = cb[o] + sum_i W[o,i]  * v[256*((c+i)&7)+q, r]  (q=m/9, r=m%9)
//                         + sum_j W[o,9+j]* x[bb_j*43+20+(4j+m)%23],
//                           bb_j = (256c + (2304j+m)/23) & 2047
__global__ void __launch_bounds__(THREADS) k_all(
    const float* __restrict__ x,
    const float* __restrict__ fc_w, const float* __restrict__ fc_b,
    const float* __restrict__ oh_w, const float* __restrict__ oh_b,
    const float* __restrict__ ot_w, const float* __restrict__ ot_b,
    const float* __restrict__ all_w, const float* __restrict__ all_b,
    float* __restrict__ out)
{
    extern __shared__ __align__(16) float sm[];
    float* s_v    = sm + OFF_V;
    float* s_fcw  = sm + OFF_FCW;
    float* s_W    = sm + OFF_W;
    float* s_cb   = sm + OFF_CB;
    float* s_fcb  = sm + OFF_FCB;
    float* s_xc   = sm + OFF_XC;
    float* s_tile = sm + OFF_TILE;

    const int t  = threadIdx.x;     // 0..575
    const int c  = blockIdx.x;      // 0..7
    const int og = blockIdx.y;      // 0..7  -> channels og*4 .. og*4+3
    const int bs = blockIdx.z;      // 0..1

    // ---- stage fc_w (coalesced) + fold weights + biases --------------------
    for (int i = t; i < EMB * SC; i += THREADS) s_fcw[i] = fc_w[i];
    for (int idx = t; idx < OUTC * 32; idx += THREADS) {
        int o = idx >> 5, i = idx & 31;
        float s = 0.f;
        if (i < EMB) {
            #pragma unroll
            for (int cc = 0; cc < EMB; cc++)
                s += all_w[o * 32 + cc] * oh_w[cc * EMB + i];
        } else {
            int j = i - EMB;
            #pragma unroll
            for (int cc = 0; cc < NOTH; cc++)
                s += all_w[o * 32 + EMB + cc] * ot_w[cc * NOTH + j];
        }
        s_W[idx] = s;
    }
    if (t < OUTC) {
        float cb = all_b[t];
        #pragma unroll
        for (int cc = 0; cc < EMB; cc++)  cb += all_w[t * 32 + cc] * oh_b[cc];
        #pragma unroll
        for (int cc = 0; cc < NOTH; cc++) cb += all_w[t * 32 + EMB + cc] * ot_b[cc];
        s_cb[t] = cb;
    }
    if (t < EMB) s_fcb[t] = fc_b[t];
    __syncthreads();    // s_fcw, s_fcb ready

    // ---- all 2048 embedding rows, 16 chunks of 128 rows --------------------
    for (int ch = 0; ch < 16; ch++) {
        // coalesced stage of 128 x-rows (5504 floats = 1376 float4)
        const float4* src = (const float4*)(x + (size_t)ch * 128 * XSTR);
        float4* dst = (float4*)s_xc;
        for (int i = t; i < 128 * XSTR / 4; i += THREADS) dst[i] = src[i];
        __syncthreads();

        // 1152 work items = (row 0..127) x (e 0..8), 2 per thread
        #pragma unroll
        for (int wi = 0; wi < 2; wi++) {
            int w   = t + THREADS * wi;      // 0..1151
            int row = w & 127;
            int e   = w >> 7;                // 0..8
            const float* xr = s_xc + row * XSTR;
            float acc = s_fcb[e];
            #pragma unroll
            for (int j = 0; j < NOH; j++) {
                int id = (int)xr[j];
                acc += s_fcw[e * SC + j * NC + id];
            }
            s_v[(ch * 128 + row) * EMB + e] = acc;
        }
        __syncthreads();
    }

    // ---- compute tile: channels og*4..og*4+3, all m ------------------------
    const int o0 = og * 4;
    #pragma unroll
    for (int mi = 0; mi < 4; mi++) {
        int m = t + THREADS * mi;            // covers 0..2303
        int q = m / 9;
        int r = m - 9 * q;

        float g[32];
        #pragma unroll
        for (int i = 0; i < 9; i++)
            g[i] = s_v[(256 * ((c + i) & 7) + q) * EMB + r];
        #pragma unroll
        for (int j = 0; j < 23; j++) {
            int eo = (4 * j + m) % 23;
            int T  = (2304 * j + m) / 23;
            int bb = (256 * c + T) & 2047;
            g[9 + j] = x[bb * XSTR + NOH + eo];
        }

        #pragma unroll
        for (int chn = 0; chn < 4; chn++) {
            int o = o0 + chn;
            const float4* W4 = (const float4*)(s_W + o * 32);
            float s = s_cb[o];
            #pragma unroll
            for (int j4 = 0; j4 < 8; j4++) {
                float4 w = W4[j4];
                s += w.x * g[4 * j4]     + w.y * g[4 * j4 + 1]
                   + w.z * g[4 * j4 + 2] + w.w * g[4 * j4 + 3];
            }
            s_tile[chn * HW + m] = s;
        }
    }
    __syncthreads();

    // ---- stage tile in registers (2304 float4 = 576 x 4) -------------------
    const float4* tile4 = (const float4*)s_tile;
    float4 r0 = tile4[t];
    float4 r1 = tile4[t + 576];
    float4 r2 = tile4[t + 1152];
    float4 r3 = tile4[t + 1728];

    // ---- store: 36 KB contiguous per batch, staggered batch order ----------
    const int cta   = c + 8 * og + 64 * bs;         // 0..127, unique
    const int start = (cta * 37) & 127;             // coprime -> bijection

    float4* __restrict__ out4 = (float4*)out
        + (size_t)(c + 1024 * bs) * (SLABSZ / 4)    // b = c + 8*(bs*128)
        + (size_t)og * 2304;                        // 4 channels per og

    #pragma unroll 4
    for (int vv = 0; vv < 128; vv++) {
        int u = (vv + start) & 127;
        float4* __restrict__ dst = out4 + (size_t)u * (8 * SLABSZ / 4);
        dst[t]        = r0;
        dst[t + 576]  = r1;
        dst[t + 1152] = r2;
        dst[t + 1728] = r3;
    }
}

// ---------------------------------------------------------------------------
extern "C" void kernel_launch(void* const* d_in, const int* in_sizes, int n_in,
                              void* d_out, int out_size) {
    const float* x     = (const float*)d_in[0];
    const float* fc_w  = (const float*)d_in[1];
    const float* fc_b  = (const float*)d_in[2];
    const float* oh_w  = (const float*)d_in[3];
    const float* oh_b  = (const float*)d_in[4];
    const float* ot_w  = (const float*)d_in[5];
    const float* ot_b  = (const float*)d_in[6];
    const float* all_w = (const float*)d_in[7];
    const float* all_b = (const float*)d_in[8];
    float* out = (float*)d_out;

    cudaFuncSetAttribute(k_all, cudaFuncAttributeMaxDynamicSharedMemorySize,
                         SMEM_FLOATS * sizeof(float));

    dim3 grid(8, 8, 2);   // 128 CTAs, single wave, 1 CTA/SM
    k_all<<<grid, THREADS, SMEM_FLOATS * sizeof(float)>>>(
        x, fc_w, fc_b, oh_w, oh_b, ot_w, ot_b, all_w, all_b, out);
}

// round 10
// speedup vs baseline: 1.3502x; 1.3502x over previous
#include <cuda_runtime.h>

#define NB     2048
#define NOH    20
#define NOTH   23
#define NC     10
#define SC     200      // NOH*NC
#define EMB    9
#define OUTC   32
#define XSTR   43       // NOH + NOTH
#define HW     2304     // 48*48
#define SLABSZ 73728    // OUTC*HW floats per batch

#define THREADS 1024

// Single fused, single-wave kernel.
// Grid (18 mtiles, 8 residue classes) = 144 CTAs x 1024 threads (1 CTA/SM,
// 32 warps/SM -- 2x R4's warp count; store MLP is the R4->R3 differentiator).
//
// Verified identities (rel_err ~1.4e-7, R1-R7):
//   out[b][o][m] depends on b only through c = b & 7
//   three 1x1 convs fold into one 32x32 weight W + bias cb
//   slab[c][o][m] = cb[o] + sum_i W[o,i]  * v[256*((c+i)&7)+q, r]  (q=m/9, r=m%9)
//                         + sum_j W[o,9+j]* x[bb_j*43+20+(4j+m)%23],
//                           bb_j = (256c + (2304j+m)/23) & 2047
__global__ void __launch_bounds__(THREADS, 1) k_all(
    const float* __restrict__ x,
    const float* __restrict__ fc_w, const float* __restrict__ fc_b,
    const float* __restrict__ oh_w, const float* __restrict__ oh_b,
    const float* __restrict__ ot_w, const float* __restrict__ ot_b,
    const float* __restrict__ all_w, const float* __restrict__ all_b,
    float* __restrict__ out)
{
    __shared__ __align__(16) float s_fcw[EMB * SC];    // 7.2 KB
    __shared__ __align__(16) float s_W[OUTC * 32];     // fused weight
    __shared__ float s_cb[OUTC];                       // fused bias
    __shared__ float s_v[8][16][EMB];                  // embedding rows this tile needs
    __shared__ __align__(16) float s_out[OUTC * 128];  // 16 KB tile [o][m_local]

    const int t     = threadIdx.x;       // 0..1023
    const int mtile = blockIdx.x;        // 0..17
    const int c     = blockIdx.y;        // 0..7

    // ---- stage fc_w (coalesced) --------------------------------------------
    for (int i = t; i < EMB * SC; i += THREADS) s_fcw[i] = fc_w[i];

    // ---- fold the three convs into one 32x32 weight + bias (1 entry/thread)
    {
        int o = t >> 5, i = t & 31;
        float s = 0.f;
        if (i < EMB) {
            #pragma unroll
            for (int cc = 0; cc < EMB; cc++)
                s += all_w[o * 32 + cc] * oh_w[cc * EMB + i];
        } else {
            int j = i - EMB;
            #pragma unroll
            for (int cc = 0; cc < NOTH; cc++)
                s += all_w[o * 32 + EMB + cc] * ot_w[cc * NOTH + j];
        }
        s_W[t] = s;
    }
    if (t < OUTC) {
        float cb = all_b[t];
        #pragma unroll
        for (int cc = 0; cc < EMB; cc++)  cb += all_w[t * 32 + cc] * oh_b[cc];
        #pragma unroll
        for (int cc = 0; cc < NOTH; cc++) cb += all_w[t * 32 + EMB + cc] * ot_b[cc];
        s_cb[t] = cb;
    }
    __syncthreads();    // s_fcw ready

    // ---- embedding rows needed by this m-tile (<=128 rows, 1 per thread) ---
    const int m0 = mtile * 128;
    const int q0 = m0 / 9;
    const int nq = (m0 + 127) / 9 - q0 + 1;   // <= 16

    if (t < 8 * nq) {
        int k  = t / nq;
        int ql = t - k * nq;
        int b  = 256 * k + q0 + ql;
        const float* xr = x + b * XSTR;       // 20 consecutive floats (~3 lines)
        float acc[EMB];
        #pragma unroll
        for (int e = 0; e < EMB; e++) acc[e] = fc_b[e];
        #pragma unroll
        for (int j = 0; j < NOH; j++) {
            int id   = (int)xr[j];
            int base = j * NC + id;
            #pragma unroll
            for (int e = 0; e < EMB; e++) acc[e] += s_fcw[e * SC + base];
        }
        #pragma unroll
        for (int e = 0; e < EMB; e++) s_v[k][ql][e] = acc[e];
    }
    __syncthreads();    // s_W, s_cb, s_v ready

    // ---- compute tile: thread -> (m_local = t&127, 4 channels) -------------
    {
        const int ml = t & 127;
        const int o0 = (t >> 7) * 4;          // 8 groups of 4 channels
        const int m  = m0 + ml;
        const int q  = m / 9;
        const int r  = m - 9 * q;
        const int ql = q - q0;

        float g[32];
        #pragma unroll
        for (int i = 0; i < 9; i++)
            g[i] = s_v[(c + i) & 7][ql][r];
        #pragma unroll
        for (int j = 0; j < 23; j++) {
            int eo = (4 * j + m) % 23;
            int T  = (2304 * j + m) / 23;
            int bb = (256 * c + T) & 2047;
            g[9 + j] = x[bb * XSTR + NOH + eo];
        }

        #pragma unroll
        for (int chn = 0; chn < 4; chn++) {
            int o = o0 + chn;
            const float4* W4 = (const float4*)(s_W + o * 32);
            float s = s_cb[o];
            #pragma unroll
            for (int j4 = 0; j4 < 8; j4++) {
                float4 w = W4[j4];
                s += w.x * g[4 * j4]     + w.y * g[4 * j4 + 1]
                   + w.z * g[4 * j4 + 2] + w.w * g[4 * j4 + 3];
            }
            s_out[o * 128 + ml] = s;
        }
    }
    __syncthreads();    // tile ready (4096 floats = 1024 float4)

    // ---- store phase: each thread owns exactly ONE float4 ------------------
    // float4 index f = t : o = f>>5, ml4 = f&31
    const float4 r0 = ((const float4*)s_out)[t];
    const int o   = t >> 5;
    const int ml4 = t & 31;

    float4* __restrict__ base = (float4*)out
        + (size_t)c * (SLABSZ / 4)            // batch residue component
        + (size_t)o * (HW / 4)                // channel
        + (size_t)(m0 >> 2) + ml4;            // spatial

    // stagger batch order per CTA to decorrelate chip-wide write windows
    const int cta   = mtile + 18 * c;         // 0..143
    const int start = (cta * 151) & 255;

    #pragma unroll 4
    for (int vv = 0; vv < 256; vv++) {
        int u = (vv + start) & 255;           // b = c + 8u
        base[(size_t)u * (8 * SLABSZ / 4)] = r0;
    }
}

// ---------------------------------------------------------------------------
extern "C" void kernel_launch(void* const* d_in, const int* in_sizes, int n_in,
                              void* d_out, int out_size) {
    const float* x     = (const float*)d_in[0];
    const float* fc_w  = (const float*)d_in[1];
    const float* fc_b  = (const float*)d_in[2];
    const float* oh_w  = (const float*)d_in[3];
    const float* oh_b  = (const float*)d_in[4];
    const float* ot_w  = (const float*)d_in[5];
    const float* ot_b  = (const float*)d_in[6];
    const float* all_w = (const float*)d_in[7];
    const float* all_b = (const float*)d_in[8];
    float* out = (float*)d_out;

    dim3 grid(18, 8);   // 144 CTAs, single wave, 1 CTA/SM, 32 warps/SM
    k_all<<<grid, THREADS>>>(x, fc_w, fc_b, oh_w, oh_b, ot_w, ot_b,
                             all_w, all_b, out);
}